// round 15
// baseline (speedup 1.0000x reference)
#include <cuda_runtime.h>
#include <cuda_fp16.h>
#include <cstdint>
#include <math.h>

#define NB 4
#define NS 2048
#define NE 1024
#define NH 16
#define NHD 64

// Scratch (allocation-free rules: __device__ globals), all fp16
__device__ __align__(256) __half g_Qh[(size_t)NB * NS * NE];
__device__ __align__(256) __half g_Wph[(size_t)NE * 3 * NE];
__device__ __align__(256) __half g_Woh[(size_t)NE * NE];
__device__ __align__(256) __half g_qkvh[(size_t)NB * NS * 3 * NE];
__device__ __align__(256) __half g_attnh[(size_t)NB * NS * NE];

__device__ __forceinline__ uint32_t f2h2(float lo, float hi) {
    __half2 h = __floats2half2_rn(lo, hi);
    return *(uint32_t*)&h;
}

__device__ __forceinline__ void mma_f16(float* c, const uint32_t* a, uint32_t b0, uint32_t b1) {
    asm volatile(
        "mma.sync.aligned.m16n8k16.row.col.f32.f16.f16.f32 "
        "{%0,%1,%2,%3},{%4,%5,%6,%7},{%8,%9},{%0,%1,%2,%3};\n"
        : "+f"(c[0]), "+f"(c[1]), "+f"(c[2]), "+f"(c[3])
        : "r"(a[0]), "r"(a[1]), "r"(a[2]), "r"(a[3]), "r"(b0), "r"(b1));
}

__device__ __forceinline__ void ldsm_x4(uint32_t* r, uint32_t addr) {
    asm volatile("ldmatrix.sync.aligned.m8n8.x4.shared.b16 {%0,%1,%2,%3}, [%4];"
        : "=r"(r[0]), "=r"(r[1]), "=r"(r[2]), "=r"(r[3]) : "r"(addr));
}
__device__ __forceinline__ void ldsm_x4_t(uint32_t* r, uint32_t addr) {
    asm volatile("ldmatrix.sync.aligned.m8n8.x4.trans.shared.b16 {%0,%1,%2,%3}, [%4];"
        : "=r"(r[0]), "=r"(r[1]), "=r"(r[2]), "=r"(r[3]) : "r"(addr));
}

__device__ __forceinline__ uint32_t smem_u32(const void* p) {
    return (uint32_t)__cvta_generic_to_shared(p);
}

__device__ __forceinline__ void cp16(uint32_t dst, const void* src) {
    asm volatile("cp.async.cg.shared.global [%0], [%1], 16;" :: "r"(dst), "l"(src) : "memory");
}
#define CP_COMMIT() asm volatile("cp.async.commit_group;" ::: "memory")
#define CP_WAIT0()  asm volatile("cp.async.wait_group 0;" ::: "memory")
#define CP_WAIT1()  asm volatile("cp.async.wait_group 1;" ::: "memory")

// A tile [m 128][k 32 halves] = 4 chunks/row.  2-row/128B atoms,
// slot = ((m&1)*4 + c) ^ ((m>>1)&7).  cp.async phases and LDSM 8-row
// reads conflict-free (hand-checked).  Chunk pair (0,1)->(2,3) = ^32.
__device__ __forceinline__ int a_off(int m, int c) {
    return ((m >> 1) * 32) + 4 * ((((m & 1) << 2) + c) ^ ((m >> 1) & 7));
}
// B tile [k 32][n 128 halves] = 16 chunks/row, perm = c ^ (r&7).
// ldsm.trans 8-row reads conflict-free; chunk+2 = ^32; k+16 = +4096B.
__device__ __forceinline__ int b_off(int r, int c) {
    return r * 64 + ((c ^ (r & 7)) << 2);
}
// Attention K/V tile [kv 64][d 64 halves] = 8 chunks/row, perm = c ^ (r&7).
__device__ __forceinline__ int k_off(int r, int c) {
    return r * 32 + ((c ^ (r & 7)) << 2);
}

// ---------------------------------------------------------------------------
__global__ void f2h_kernel(const float* __restrict__ s, __half* __restrict__ d, int n4)
{
    int i = blockIdx.x * blockDim.x + threadIdx.x;
    if (i < n4) {
        float4 v = ((const float4*)s)[i];
        uint2 h = { f2h2(v.x, v.y), f2h2(v.z, v.w) };
        ((uint2*)d)[i] = h;
    }
}

// ---------------------------------------------------------------------------
// C[M,N] = A[M,K] @ B[K,N] + bias.  fp16 in, fp32 accum, OUT_HALF selects
// fp16 or fp32 C.  Block 128x128, K-tile 32, 8 warps (2x4), warp 64x32.
// THREE-stage cp.async pipeline (one commit group per k-tile, empty groups
// on non-prefetch iters so wait_group 1 always certifies the current tile).
// ---------------------------------------------------------------------------
template<bool OUT_HALF>
__global__ __launch_bounds__(256, 2)
void gemm_h(const __half* __restrict__ A, const __half* __restrict__ B,
            const float* __restrict__ bias, void* __restrict__ Cv,
            int M, int N, int K)
{
    __shared__ __align__(16) uint32_t As[3][2048];   // 8KB/stage
    __shared__ __align__(16) uint32_t Bs[3][2048];   // 8KB/stage

    const int tid  = threadIdx.x;
    const int w    = tid >> 5;
    const int lane = tid & 31;
    const int g    = lane >> 2;
    const int tig  = lane & 3;
    const int wm   = w >> 2;
    const int wn   = w & 3;
    const int bm   = blockIdx.y * 128;
    const int bn   = blockIdx.x * 128;

    // A cp.async: thread -> row tid>>1, chunks (tid&1)*2, +1
    const int ar  = tid >> 1;
    const int acb = (tid & 1) * 2;
    const __half* Ag = A + (size_t)(bm + ar) * K + acb * 8;
    const uint32_t aD0 = smem_u32(&As[0][a_off(ar, acb)]);
    const uint32_t aD1 = smem_u32(&As[0][a_off(ar, acb + 1)]);

    // B cp.async: rows tid>>4, +16; chunk tid&15
    const int brr = tid >> 4;
    const int bcc = tid & 15;
    const __half* Bg0 = B + (size_t)brr * N + bn + bcc * 8;
    const __half* Bg1 = Bg0 + (size_t)16 * N;
    const uint32_t bD0 = smem_u32(&Bs[0][b_off(brr, bcc)]);
    const uint32_t bD1 = smem_u32(&Bs[0][b_off(brr + 16, bcc)]);

    // ldmatrix addresses (loop-invariant)
    const int alr = lane & 15, alc = lane >> 4;
    uint32_t aL[4];
    #pragma unroll
    for (int mt = 0; mt < 4; mt++)
        aL[mt] = smem_u32(&As[0][a_off(wm * 64 + mt * 16 + alr, alc)]);
    const uint32_t bL = smem_u32(&Bs[0][b_off(lane & 15, wn * 4 + (lane >> 4))]);

    // prologue: tiles 0 and 1 -> stages 0, 1 (one commit group each)
    {
        cp16(aD0, Ag);  cp16(aD1, Ag + 8);
        cp16(bD0, Bg0); cp16(bD1, Bg1);
        CP_COMMIT();
        cp16(aD0 + 8192u, Ag + 32);
        cp16(aD1 + 8192u, Ag + 40);
        cp16(bD0 + 8192u, Bg0 + (size_t)32 * N);
        cp16(bD1 + 8192u, Bg1 + (size_t)32 * N);
        CP_COMMIT();
    }

    float acc[4][4][4];
    #pragma unroll
    for (int mt = 0; mt < 4; mt++)
        #pragma unroll
        for (int nt = 0; nt < 4; nt++)
            #pragma unroll
            for (int i = 0; i < 4; i++) acc[mt][nt][i] = 0.f;

    const int nIter = K / 32;
    int stage = 0, pstage = 2;   // compute stage; prefetch stage
    for (int it = 0; it < nIter; it++) {
        CP_WAIT1();              // oldest pending group (= tile it) landed
        __syncthreads();         // all warps done reading stage being overwritten
        if (it + 2 < nIter) {
            const int kn = (it + 2) * 32;
            const uint32_t off = (uint32_t)pstage * 8192u;
            cp16(aD0 + off, Ag + kn);
            cp16(aD1 + off, Ag + kn + 8);
            cp16(bD0 + off, Bg0 + (size_t)kn * N);
            cp16(bD1 + off, Bg1 + (size_t)kn * N);
        }
        CP_COMMIT();             // empty group when no prefetch (keeps wait_group 1 exact)
        const uint32_t bo = (uint32_t)stage * 8192u;
        #pragma unroll
        for (int ks = 0; ks < 2; ks++) {
            const uint32_t kx = (uint32_t)ks << 5;
            uint32_t af[4][4], bq0[4], bq1[4];
            #pragma unroll
            for (int mt = 0; mt < 4; mt++)
                ldsm_x4(af[mt], (aL[mt] + bo) ^ kx);
            const uint32_t bAdr = bL + bo + ks * 4096u;
            ldsm_x4_t(bq0, bAdr);
            ldsm_x4_t(bq1, bAdr ^ 32u);
            #pragma unroll
            for (int mt = 0; mt < 4; mt++) {
                mma_f16(acc[mt][0], af[mt], bq0[0], bq0[1]);
                mma_f16(acc[mt][1], af[mt], bq0[2], bq0[3]);
                mma_f16(acc[mt][2], af[mt], bq1[0], bq1[1]);
                mma_f16(acc[mt][3], af[mt], bq1[2], bq1[3]);
            }
        }
        stage  = (stage == 2)  ? 0 : stage + 1;
        pstage = (pstage == 2) ? 0 : pstage + 1;
    }

    // epilogue
    #pragma unroll
    for (int mt = 0; mt < 4; mt++) {
        const int row = bm + wm * 64 + mt * 16 + g;
        #pragma unroll
        for (int nt = 0; nt < 4; nt++) {
            const int col = bn + wn * 32 + nt * 8 + 2 * tig;
            const float bv0 = __ldg(bias + col), bv1 = __ldg(bias + col + 1);
            if (OUT_HALF) {
                __half* C = (__half*)Cv;
                *(uint32_t*)(C + (size_t)row * N + col)       = f2h2(acc[mt][nt][0] + bv0, acc[mt][nt][1] + bv1);
                *(uint32_t*)(C + (size_t)(row + 8) * N + col) = f2h2(acc[mt][nt][2] + bv0, acc[mt][nt][3] + bv1);
            } else {
                float* C = (float*)Cv;
                float2 v0 = { acc[mt][nt][0] + bv0, acc[mt][nt][1] + bv1 };
                float2 v1 = { acc[mt][nt][2] + bv0, acc[mt][nt][3] + bv1 };
                *(float2*)(C + (size_t)row * N + col) = v0;
                *(float2*)(C + (size_t)(row + 8) * N + col) = v1;
            }
        }
    }
}

// ---------------------------------------------------------------------------
// Causal flash attention, fp16 qkv in, fp16 out.  One block per
// (qtile=64, head, batch), 4 warps.  cp.async double-buffered K/V tiles;
// K via ldmatrix, V via ldmatrix.trans; P stays in registers.
// ---------------------------------------------------------------------------
__global__ __launch_bounds__(128)
void attn_h(const __half* __restrict__ qkv, __half* __restrict__ outp)
{
    __shared__ __align__(16) uint32_t Ks[2][2048];   // 8KB/buf
    __shared__ __align__(16) uint32_t Vs[2][2048];

    const int tid  = threadIdx.x;
    const int w    = tid >> 5;
    const int lane = tid & 31;
    const int g    = lane >> 2;
    const int tig  = lane & 3;
    const int qt   = blockIdx.x;
    const int h    = blockIdx.y;
    const int b    = blockIdx.z;

    const size_t rs = 3 * NE;
    const __half* base = qkv + (size_t)b * NS * rs;
    const __half* qptr = base + h * NHD;
    const __half* kptr = base + NE + h * NHD;
    const __half* vptr = base + 2 * NE + h * NHD;

    const int qrow0 = qt * 64 + w * 16;

    // Q fragments (x 0.125 exact in fp16)
    const __half2 s8 = __floats2half2_rn(0.125f, 0.125f);
    uint32_t qf[4][4];
    #pragma unroll
    for (int kt = 0; kt < 4; kt++) {
        const int d0 = kt * 16 + 2 * tig;
        const __half* r0 = qptr + (size_t)(qrow0 + g) * rs;
        const __half* r1 = qptr + (size_t)(qrow0 + g + 8) * rs;
        __half2 h0 = __hmul2(*(const __half2*)(r0 + d0), s8);
        __half2 h1 = __hmul2(*(const __half2*)(r1 + d0), s8);
        __half2 h2 = __hmul2(*(const __half2*)(r0 + d0 + 8), s8);
        __half2 h3 = __hmul2(*(const __half2*)(r1 + d0 + 8), s8);
        qf[kt][0] = *(uint32_t*)&h0; qf[kt][1] = *(uint32_t*)&h1;
        qf[kt][2] = *(uint32_t*)&h2; qf[kt][3] = *(uint32_t*)&h3;
    }

    // cp.async mapping: chunk c = tid&7 fixed; rows r_i = tid>>3 + 16*i
    const int cc = tid & 7;
    const int r0i = tid >> 3;
    uint32_t kD[4], vD[4];
    size_t srcOff[4];
    #pragma unroll
    for (int i = 0; i < 4; i++) {
        const int r = r0i + 16 * i;
        kD[i] = smem_u32(&Ks[0][k_off(r, cc)]);
        vD[i] = smem_u32(&Vs[0][k_off(r, cc)]);
        srcOff[i] = (size_t)r * rs + cc * 8;
    }

    // ldmatrix bases
    const int klr = ((lane >> 4) << 3) + (lane & 7);
    const int klc = (lane >> 3) & 1;
    const uint32_t kBase = smem_u32(&Ks[0][k_off(klr, klc)]);
    const int vlr = lane & 15;
    const int vlc = lane >> 4;
    const uint32_t vBase = smem_u32(&Vs[0][k_off(vlr, vlc)]);

    float o[8][4];
    #pragma unroll
    for (int nt = 0; nt < 8; nt++)
        #pragma unroll
        for (int i = 0; i < 4; i++) o[nt][i] = 0.f;
    float m0 = -INFINITY, m1 = -INFINITY;
    float l0 = 0.f, l1 = 0.f;

    // prologue: j = 0 -> buffer 0
    #pragma unroll
    for (int i = 0; i < 4; i++) {
        cp16(kD[i], kptr + srcOff[i]);
        cp16(vD[i], vptr + srcOff[i]);
    }
    CP_COMMIT();

    int buf = 0;
    for (int j = 0; j <= qt; j++) {
        CP_WAIT0();
        __syncthreads();
        if (j < qt) {
            const uint32_t off = (uint32_t)(buf ^ 1) * 8192u;
            const size_t jo = (size_t)(j + 1) * 64 * rs;
            #pragma unroll
            for (int i = 0; i < 4; i++) {
                cp16(kD[i] + off, kptr + jo + srcOff[i]);
                cp16(vD[i] + off, vptr + jo + srcOff[i]);
            }
            CP_COMMIT();
        }
        const uint32_t bo = (uint32_t)buf * 8192u;

        // S = Q @ K^T  (16 x 64 per warp)
        float sc[8][4];
        #pragma unroll
        for (int nt = 0; nt < 8; nt++)
            #pragma unroll
            for (int i = 0; i < 4; i++) sc[nt][i] = 0.f;
        #pragma unroll
        for (int kt = 0; kt < 4; kt++) {
            #pragma unroll
            for (int p = 0; p < 4; p++) {
                uint32_t bq[4];
                ldsm_x4(bq, (kBase + bo + p * 2048u) ^ ((uint32_t)kt << 5));
                mma_f16(sc[2 * p],     qf[kt], bq[0], bq[1]);
                mma_f16(sc[2 * p + 1], qf[kt], bq[2], bq[3]);
            }
        }

        if (j == qt) {
            const int r0g = qrow0 + g, r1g = qrow0 + g + 8;
            #pragma unroll
            for (int nt = 0; nt < 8; nt++) {
                const int col = j * 64 + nt * 8 + 2 * tig;
                if (col     > r0g) sc[nt][0] = -1e30f;
                if (col + 1 > r0g) sc[nt][1] = -1e30f;
                if (col     > r1g) sc[nt][2] = -1e30f;
                if (col + 1 > r1g) sc[nt][3] = -1e30f;
            }
        }

        float mt0 = -1e30f, mt1 = -1e30f;
        #pragma unroll
        for (int nt = 0; nt < 8; nt++) {
            mt0 = fmaxf(mt0, fmaxf(sc[nt][0], sc[nt][1]));
            mt1 = fmaxf(mt1, fmaxf(sc[nt][2], sc[nt][3]));
        }
        mt0 = fmaxf(mt0, __shfl_xor_sync(0xffffffffu, mt0, 1));
        mt0 = fmaxf(mt0, __shfl_xor_sync(0xffffffffu, mt0, 2));
        mt1 = fmaxf(mt1, __shfl_xor_sync(0xffffffffu, mt1, 1));
        mt1 = fmaxf(mt1, __shfl_xor_sync(0xffffffffu, mt1, 2));

        const float mn0 = fmaxf(m0, mt0), mn1 = fmaxf(m1, mt1);
        const float al0 = __expf(m0 - mn0), al1 = __expf(m1 - mn1);
        m0 = mn0; m1 = mn1;

        uint32_t ph[8][2];
        float rs0 = 0.f, rs1 = 0.f;
        #pragma unroll
        for (int nt = 0; nt < 8; nt++) {
            const float p0 = __expf(sc[nt][0] - mn0);
            const float p1 = __expf(sc[nt][1] - mn0);
            const float p2 = __expf(sc[nt][2] - mn1);
            const float p3 = __expf(sc[nt][3] - mn1);
            rs0 += p0 + p1;
            rs1 += p2 + p3;
            ph[nt][0] = f2h2(p0, p1);
            ph[nt][1] = f2h2(p2, p3);
            o[nt][0] *= al0; o[nt][1] *= al0;
            o[nt][2] *= al1; o[nt][3] *= al1;
        }
        rs0 += __shfl_xor_sync(0xffffffffu, rs0, 1);
        rs0 += __shfl_xor_sync(0xffffffffu, rs0, 2);
        rs1 += __shfl_xor_sync(0xffffffffu, rs1, 1);
        rs1 += __shfl_xor_sync(0xffffffffu, rs1, 2);
        l0 = l0 * al0 + rs0;
        l1 = l1 * al1 + rs1;

        // O += P @ V
        #pragma unroll
        for (int kt = 0; kt < 4; kt++) {
            uint32_t pa[4] = { ph[2 * kt][0], ph[2 * kt][1],
                               ph[2 * kt + 1][0], ph[2 * kt + 1][1] };
            #pragma unroll
            for (int p = 0; p < 4; p++) {
                uint32_t vq[4];
                ldsm_x4_t(vq, (vBase + bo + kt * 2048u) ^ ((uint32_t)p << 5));
                mma_f16(o[2 * p],     pa, vq[0], vq[1]);
                mma_f16(o[2 * p + 1], pa, vq[2], vq[3]);
            }
        }
        buf ^= 1;
    }

    const float inv0 = 1.f / l0, inv1 = 1.f / l1;
    const size_t orow0 = (size_t)b * NS + qrow0 + g;
    #pragma unroll
    for (int nt = 0; nt < 8; nt++) {
        const int col = h * NHD + nt * 8 + 2 * tig;
        *(uint32_t*)(outp + orow0 * NE + col)       = f2h2(o[nt][0] * inv0, o[nt][1] * inv0);
        *(uint32_t*)(outp + (orow0 + 8) * NE + col) = f2h2(o[nt][2] * inv1, o[nt][3] * inv1);
    }
}

// ---------------------------------------------------------------------------
extern "C" void kernel_launch(void* const* d_in, const int* in_sizes, int n_in,
                              void* d_out, int out_size)
{
    (void)in_sizes; (void)n_in; (void)out_size;
    const float* Q  = (const float*)d_in[0];
    const float* Wp = (const float*)d_in[1];
    const float* bp = (const float*)d_in[2];
    const float* Wo = (const float*)d_in[3];
    const float* bo = (const float*)d_in[4];
    float* out = (float*)d_out;

    void *qh, *wph, *woh, *qkvh, *attnh;
    cudaGetSymbolAddress(&qh, g_Qh);
    cudaGetSymbolAddress(&wph, g_Wph);
    cudaGetSymbolAddress(&woh, g_Woh);
    cudaGetSymbolAddress(&qkvh, g_qkvh);
    cudaGetSymbolAddress(&attnh, g_attnh);

    const int M = NB * NS;  // 8192

    const int nQ  = M * NE / 4;
    const int nWp = NE * 3 * NE / 4;
    const int nWo = NE * NE / 4;
    f2h_kernel<<<(nQ  + 255) / 256, 256>>>(Q,  (__half*)qh,  nQ);
    f2h_kernel<<<(nWp + 255) / 256, 256>>>(Wp, (__half*)wph, nWp);
    f2h_kernel<<<(nWo + 255) / 256, 256>>>(Wo, (__half*)woh, nWo);

    gemm_h<true><<<dim3((3 * NE) / 128, M / 128), 256>>>(
        (const __half*)qh, (const __half*)wph, bp, qkvh, M, 3 * NE, NE);
    attn_h<<<dim3(NS / 64, NH, NB), 128>>>((const __half*)qkvh, (__half*)attnh);
    gemm_h<false><<<dim3(NE / 128, M / 128), 256>>>(
        (const __half*)attnh, (const __half*)woh, bo, out, M, NE, NE);
}